// round 17
// baseline (speedup 1.0000x reference)
#include <cuda_runtime.h>
#include <cuda_fp16.h>
#include <cuda_pipeline.h>
#include <math.h>
#include <stdint.h>

#define BATCH 4
#define SEQ   1024
#define DIM   4096
#define NH    32
#define NKV   8
#define HD    128
#define KVD   (NKV*HD)            // 1024
#define NTOK  (BATCH*SEQ)         // 4096
#define NTOT  (DIM + 2*KVD)       // 6144 fused QKV output cols
#define SCALE 0.08838834764831845f

#define STR  72                   // A smem stride (halves)
#define BSTR 136                  // B smem stride (halves)
#define FSTR 136                  // flash smem stride (halves)

typedef __half half_t;

// ---------------- scratch (device globals) ----------------
__device__ half_t g_xh [(size_t)NTOK * DIM];
__device__ half_t g_wqh[(size_t)DIM * DIM];     // natural [K,N] fp16
__device__ half_t g_wkh[(size_t)DIM * KVD];
__device__ half_t g_wvh[(size_t)DIM * KVD];
__device__ half_t g_woh[(size_t)DIM * DIM];
__device__ half_t g_Qh [(size_t)NTOK * DIM];
__device__ half_t g_Kh [(size_t)NTOK * KVD];
__device__ half_t g_Vh [(size_t)NTOK * KVD];
__device__ half_t g_Ah [(size_t)NTOK * DIM];

// ---------------- mma.sync helpers ----------------
__device__ __forceinline__ void ldsm4(uint32_t* r, const half_t* p) {
    uint32_t a = (uint32_t)__cvta_generic_to_shared(p);
    asm volatile("ldmatrix.sync.aligned.m8n8.x4.shared.b16 {%0,%1,%2,%3}, [%4];"
        : "=r"(r[0]), "=r"(r[1]), "=r"(r[2]), "=r"(r[3]) : "r"(a));
}
__device__ __forceinline__ void ldsm4t(uint32_t* r, const half_t* p) {
    uint32_t a = (uint32_t)__cvta_generic_to_shared(p);
    asm volatile("ldmatrix.sync.aligned.m8n8.x4.trans.shared.b16 {%0,%1,%2,%3}, [%4];"
        : "=r"(r[0]), "=r"(r[1]), "=r"(r[2]), "=r"(r[3]) : "r"(a));
}
__device__ __forceinline__ void mma16816(float* c, const uint32_t* a, uint32_t b0, uint32_t b1) {
    asm volatile("mma.sync.aligned.m16n8k16.row.col.f32.f16.f16.f32 "
        "{%0,%1,%2,%3}, {%4,%5,%6,%7}, {%8,%9}, {%0,%1,%2,%3};"
        : "+f"(c[0]), "+f"(c[1]), "+f"(c[2]), "+f"(c[3])
        : "r"(a[0]), "r"(a[1]), "r"(a[2]), "r"(a[3]), "r"(b0), "r"(b1));
}
__device__ __forceinline__ uint32_t packh2(float a, float b) {
    __half2 h = __floats2half2_rn(a, b);
    return *(uint32_t*)&h;
}

// ---------------- GEMM mainloop: 128x128 tile, 3-stage cp.async ---------------
__device__ __forceinline__ void gemm_main(const half_t* __restrict__ A, int lda,
                                          const half_t* __restrict__ B, int ldb,
                                          int bm, int bn, float acc[2][8][4])
{
    extern __shared__ half_t sm[];
    // 3 A stages, then 3 B stages
    half_t* sAb = sm;
    half_t* sBb = sm + 3 * 128 * STR;

    const int tid = threadIdx.x, warp = tid >> 5, lane = tid & 31;
    const int wm = (warp >> 1) * 32;
    const int wn = (warp & 1) * 64;

#pragma unroll
    for (int mi = 0; mi < 2; mi++)
#pragma unroll
        for (int nb = 0; nb < 8; nb++)
#pragma unroll
            for (int e = 0; e < 4; e++) acc[mi][nb][e] = 0.0f;

    auto load_tile = [&](int st, int k0) {
        half_t* sA = sAb + st * 128 * STR;
        half_t* sB = sBb + st * 64 * BSTR;
#pragma unroll
        for (int l = 0; l < 4; l++) {
            int idx = l * 256 + tid;
            int r = idx >> 3, c8 = idx & 7;
            __pipeline_memcpy_async(&sA[r * STR + c8 * 8],
                                    &A[(size_t)(bm + r) * lda + k0 + c8 * 8], 16);
        }
#pragma unroll
        for (int l = 0; l < 4; l++) {
            int idx = l * 256 + tid;
            int r = idx >> 4, c8 = idx & 15;
            __pipeline_memcpy_async(&sB[r * BSTR + c8 * 8],
                                    &B[(size_t)(k0 + r) * ldb + bn + c8 * 8], 16);
        }
    };

    const int nt = DIM / 64;
    load_tile(0, 0);
    __pipeline_commit();
    load_tile(1, 64);
    __pipeline_commit();

    int st = 0;
    for (int t = 0; t < nt; t++) {
        if (t + 2 < nt) {
            load_tile((st + 2) % 3, (t + 2) * 64);
            __pipeline_commit();
            __pipeline_wait_prior(2);
        } else if (t + 1 < nt) {
            __pipeline_wait_prior(1);
        } else {
            __pipeline_wait_prior(0);
        }
        __syncthreads();

        half_t* sA = sAb + st * 128 * STR;
        half_t* sB = sBb + st * 64 * BSTR;
#pragma unroll
        for (int kk = 0; kk < 64; kk += 16) {
            uint32_t a0[4], a1[4];
            ldsm4(a0, &sA[(wm + (lane & 15)) * STR + kk + (lane >> 4) * 8]);
            ldsm4(a1, &sA[(wm + 16 + (lane & 15)) * STR + kk + (lane >> 4) * 8]);
#pragma unroll
            for (int nb2 = 0; nb2 < 4; nb2++) {
                uint32_t bb[4];
                int kr = kk + (lane & 7) + (((lane >> 3) & 1) << 3);
                int nc = wn + nb2 * 16 + ((lane >> 4) << 3);
                ldsm4t(bb, &sB[kr * BSTR + nc]);
                mma16816(acc[0][2 * nb2],     a0, bb[0], bb[1]);
                mma16816(acc[0][2 * nb2 + 1], a0, bb[2], bb[3]);
                mma16816(acc[1][2 * nb2],     a1, bb[0], bb[1]);
                mma16816(acc[1][2 * nb2 + 1], a1, bb[2], bb[3]);
            }
        }
        __syncthreads();
        st = (st + 1) % 3;
    }
}

#define SMEM_PJ ((3 * 128 * STR + 3 * 64 * BSTR) * (int)sizeof(half_t))  // 107520 B
#define SMEM_FL (5 * 128 * FSTR * (int)sizeof(half_t))                   // 174080 B

// ---------------- fused QKV projection (one grid over N = 6144) ---------------
__global__ void __launch_bounds__(256, 2) k_qkv(const float* __restrict__ cs,
                                                const float* __restrict__ sn)
{
    const int bm = blockIdx.y * 128;
    const int bng = blockIdx.x * 128;

    const half_t* B; int ldb, bn; half_t* C; int ldc; bool rope;
    if (bng < DIM)              { B = g_wqh; ldb = DIM; bn = bng;             C = g_Qh; ldc = DIM; rope = true;  }
    else if (bng < DIM + KVD)   { B = g_wkh; ldb = KVD; bn = bng - DIM;       C = g_Kh; ldc = KVD; rope = true;  }
    else                        { B = g_wvh; ldb = KVD; bn = bng - DIM - KVD; C = g_Vh; ldc = KVD; rope = false; }

    float acc[2][8][4];
    gemm_main(g_xh, DIM, B, ldb, bm, bn, acc);

    const int lane = threadIdx.x & 31, warp = threadIdx.x >> 5;
    const int wm = (warp >> 1) * 32, wn = (warp & 1) * 64;

#pragma unroll
    for (int mi = 0; mi < 2; mi++) {
        int r0 = bm + wm + mi * 16 + (lane >> 2);
#pragma unroll
        for (int nb = 0; nb < 8; nb++) {
            int c = bn + wn + nb * 8 + (lane & 3) * 2;
            float v0 = acc[mi][nb][0], v1 = acc[mi][nb][1];
            float v2 = acc[mi][nb][2], v3 = acc[mi][nb][3];
            if (rope) {
                int i = (c & 127) >> 1;
                int s0 = r0 & (SEQ - 1), s1 = (r0 + 8) & (SEQ - 1);
                float c0 = cs[s0 * 64 + i], z0 = sn[s0 * 64 + i];
                float c1 = cs[s1 * 64 + i], z1 = sn[s1 * 64 + i];
                *(__half2*)&C[(size_t)r0 * ldc + c] =
                    __floats2half2_rn(v0 * c0 - v1 * z0, v0 * z0 + v1 * c0);
                *(__half2*)&C[(size_t)(r0 + 8) * ldc + c] =
                    __floats2half2_rn(v2 * c1 - v3 * z1, v2 * z1 + v3 * c1);
            } else {
                *(__half2*)&C[(size_t)r0 * ldc + c]       = __floats2half2_rn(v0, v1);
                *(__half2*)&C[(size_t)(r0 + 8) * ldc + c] = __floats2half2_rn(v2, v3);
            }
        }
    }
}

// ---------------- output projection -> fp32 ----------------
__global__ void __launch_bounds__(256, 2) k_projo(float* __restrict__ out)
{
    const int bm = blockIdx.y * 128, bn = blockIdx.x * 128;
    float acc[2][8][4];
    gemm_main(g_Ah, DIM, g_woh, DIM, bm, bn, acc);

    const int lane = threadIdx.x & 31, warp = threadIdx.x >> 5;
    const int wm = (warp >> 1) * 32, wn = (warp & 1) * 64;
#pragma unroll
    for (int mi = 0; mi < 2; mi++) {
        int r0 = bm + wm + mi * 16 + (lane >> 2);
#pragma unroll
        for (int nb = 0; nb < 8; nb++) {
            int c = bn + wn + nb * 8 + (lane & 3) * 2;
            *(float2*)&out[(size_t)r0 * DIM + c]       = make_float2(acc[mi][nb][0], acc[mi][nb][1]);
            *(float2*)&out[(size_t)(r0 + 8) * DIM + c] = make_float2(acc[mi][nb][2], acc[mi][nb][3]);
        }
    }
}

// ---------------- fused flash attention (unchanged, proven) ----------------
__global__ void __launch_bounds__(256, 1) k_flash() {
    int z = blockIdx.y, b = z >> 5, h = z & 31, kvh = h >> 2;
    int q0 = blockIdx.x * 128;
    const half_t* Qp = g_Qh + ((size_t)b * SEQ + q0) * DIM + h * HD;
    const half_t* Kp = g_Kh + (size_t)b * SEQ * KVD + kvh * HD;
    const half_t* Vp = g_Vh + (size_t)b * SEQ * KVD + kvh * HD;
    half_t*       Op = g_Ah + ((size_t)b * SEQ + q0) * DIM + h * HD;

    extern __shared__ half_t sm[];
    half_t* sQ = sm;
    half_t* sK = sm + 128 * FSTR;
    half_t* sV = sm + 3 * 128 * FSTR;

    const int tid = threadIdx.x, warp = tid >> 5, lane = tid & 31;
    const int q0w = warp * 16;

    for (int i = tid; i < 128 * 16; i += 256) {
        int r = i >> 4, c = i & 15;
        *(uint4*)&sQ[r * FSTR + c * 8] = *(const uint4*)&Qp[(size_t)r * DIM + c * 8];
    }

    auto loadKV = [&](int st, int t) {
        const half_t* kp = Kp + (size_t)t * 128 * KVD;
        const half_t* vp = Vp + (size_t)t * 128 * KVD;
        half_t* dk = sK + st * 128 * FSTR;
        half_t* dv = sV + st * 128 * FSTR;
#pragma unroll
        for (int l = 0; l < 8; l++) {
            int i = l * 256 + tid;
            int r = i >> 4, c = i & 15;
            __pipeline_memcpy_async(&dk[r * FSTR + c * 8], &kp[(size_t)r * KVD + c * 8], 16);
            __pipeline_memcpy_async(&dv[r * FSTR + c * 8], &vp[(size_t)r * KVD + c * 8], 16);
        }
    };

    loadKV(0, 0);
    __pipeline_commit();
    __syncthreads();

    float oacc[16][4];
#pragma unroll
    for (int j = 0; j < 16; j++)
#pragma unroll
        for (int e = 0; e < 4; e++) oacc[j][e] = 0.0f;
    float mr0 = -1e30f, mr1 = -1e30f, lr0 = 0.0f, lr1 = 0.0f;

    for (int t = 0; t < SEQ / 128; t++) {
        if (t + 1 < SEQ / 128) {
            loadKV((t + 1) & 1, t + 1);
            __pipeline_commit();
            __pipeline_wait_prior(1);
        } else {
            __pipeline_wait_prior(0);
        }
        __syncthreads();
        const half_t* kst = sK + (t & 1) * 128 * FSTR;
        const half_t* vst = sV + (t & 1) * 128 * FSTR;

        float sacc[16][4];
#pragma unroll
        for (int j = 0; j < 16; j++)
#pragma unroll
            for (int e = 0; e < 4; e++) sacc[j][e] = 0.0f;

#pragma unroll
        for (int kd = 0; kd < 8; kd++) {
            uint32_t a[4];
            ldsm4(a, &sQ[(q0w + (lane & 15)) * FSTR + kd * 16 + (lane >> 4) * 8]);
#pragma unroll
            for (int nb = 0; nb < 8; nb++) {
                uint32_t bb[4];
                int key = nb * 16 + (lane & 7) + ((lane >> 4) << 3);
                int dc  = kd * 16 + (((lane >> 3) & 1) << 3);
                ldsm4(bb, &kst[key * FSTR + dc]);
                mma16816(sacc[2 * nb],     a, bb[0], bb[1]);
                mma16816(sacc[2 * nb + 1], a, bb[2], bb[3]);
            }
        }

        float tm0 = -1e30f, tm1 = -1e30f;
#pragma unroll
        for (int j = 0; j < 16; j++) {
            sacc[j][0] *= SCALE; sacc[j][1] *= SCALE;
            sacc[j][2] *= SCALE; sacc[j][3] *= SCALE;
            tm0 = fmaxf(tm0, fmaxf(sacc[j][0], sacc[j][1]));
            tm1 = fmaxf(tm1, fmaxf(sacc[j][2], sacc[j][3]));
        }
        tm0 = fmaxf(tm0, __shfl_xor_sync(0xffffffffu, tm0, 1));
        tm0 = fmaxf(tm0, __shfl_xor_sync(0xffffffffu, tm0, 2));
        tm1 = fmaxf(tm1, __shfl_xor_sync(0xffffffffu, tm1, 1));
        tm1 = fmaxf(tm1, __shfl_xor_sync(0xffffffffu, tm1, 2));
        float mn0 = fmaxf(mr0, tm0), mn1 = fmaxf(mr1, tm1);
        float cor0 = __expf(mr0 - mn0), cor1 = __expf(mr1 - mn1);
        mr0 = mn0; mr1 = mn1;

        uint32_t ph[16][2];
        float rs0 = 0.0f, rs1 = 0.0f;
#pragma unroll
        for (int j = 0; j < 16; j++) {
            float e0 = __expf(sacc[j][0] - mn0), e1 = __expf(sacc[j][1] - mn0);
            float e2 = __expf(sacc[j][2] - mn1), e3 = __expf(sacc[j][3] - mn1);
            rs0 += e0 + e1; rs1 += e2 + e3;
            ph[j][0] = packh2(e0, e1);
            ph[j][1] = packh2(e2, e3);
        }
        rs0 += __shfl_xor_sync(0xffffffffu, rs0, 1);
        rs0 += __shfl_xor_sync(0xffffffffu, rs0, 2);
        rs1 += __shfl_xor_sync(0xffffffffu, rs1, 1);
        rs1 += __shfl_xor_sync(0xffffffffu, rs1, 2);
        lr0 = lr0 * cor0 + rs0;
        lr1 = lr1 * cor1 + rs1;
#pragma unroll
        for (int j = 0; j < 16; j++) {
            oacc[j][0] *= cor0; oacc[j][1] *= cor0;
            oacc[j][2] *= cor1; oacc[j][3] *= cor1;
        }

#pragma unroll
        for (int kk = 0; kk < 8; kk++) {
            uint32_t pa[4] = { ph[2 * kk][0], ph[2 * kk][1], ph[2 * kk + 1][0], ph[2 * kk + 1][1] };
#pragma unroll
            for (int nb = 0; nb < 8; nb++) {
                uint32_t bb[4];
                int key = kk * 16 + (lane & 7) + (((lane >> 3) & 1) << 3);
                int dc  = nb * 16 + ((lane >> 4) << 3);
                ldsm4t(bb, &vst[key * FSTR + dc]);
                mma16816(oacc[2 * nb],     pa, bb[0], bb[1]);
                mma16816(oacc[2 * nb + 1], pa, bb[2], bb[3]);
            }
        }
        __syncthreads();
    }

    float il0 = 1.0f / lr0, il1 = 1.0f / lr1;
    int r0 = q0w + (lane >> 2), c0 = (lane & 3) * 2;
#pragma unroll
    for (int j = 0; j < 16; j++) {
        __half2 h0 = __floats2half2_rn(oacc[j][0] * il0, oacc[j][1] * il0);
        __half2 h1 = __floats2half2_rn(oacc[j][2] * il1, oacc[j][3] * il1);
        *(__half2*)&Op[(size_t)r0 * DIM + j * 8 + c0] = h0;
        *(__half2*)&Op[(size_t)(r0 + 8) * DIM + j * 8 + c0] = h1;
    }
}

// ---------------- fp32 -> fp16 convert (wide: 8 halves / iter) ----------------
__global__ void k_conv(const float4* __restrict__ in, uint4* __restrict__ out, int n8) {
    for (int i = blockIdx.x * 256 + threadIdx.x; i < n8; i += gridDim.x * 256) {
        float4 a = in[2 * i], b = in[2 * i + 1];
        __half2 h0 = __floats2half2_rn(a.x, a.y);
        __half2 h1 = __floats2half2_rn(a.z, a.w);
        __half2 h2 = __floats2half2_rn(b.x, b.y);
        __half2 h3 = __floats2half2_rn(b.z, b.w);
        uint4 o;
        o.x = *(uint32_t*)&h0; o.y = *(uint32_t*)&h1;
        o.z = *(uint32_t*)&h2; o.w = *(uint32_t*)&h3;
        out[i] = o;
    }
}

// ---------------- launch ----------------
extern "C" void kernel_launch(void* const* d_in, const int* in_sizes, int n_in,
                              void* d_out, int out_size)
{
    const float* x  = (const float*)d_in[0];
    const float* fc = (const float*)d_in[1];
    const float* fs = (const float*)d_in[2];
    const float* wq = (const float*)d_in[3];
    const float* wk = (const float*)d_in[4];
    const float* wv = (const float*)d_in[5];
    const float* wo = (const float*)d_in[6];
    float* out = (float*)d_out;

    cudaFuncSetAttribute(k_qkv,   cudaFuncAttributeMaxDynamicSharedMemorySize, SMEM_PJ);
    cudaFuncSetAttribute(k_projo, cudaFuncAttributeMaxDynamicSharedMemorySize, SMEM_PJ);
    cudaFuncSetAttribute(k_flash, cudaFuncAttributeMaxDynamicSharedMemorySize, SMEM_FL);

    half_t *xh, *wqh, *wkh, *wvh, *woh;
    cudaGetSymbolAddress((void**)&xh,  g_xh);
    cudaGetSymbolAddress((void**)&wqh, g_wqh);
    cudaGetSymbolAddress((void**)&wkh, g_wkh);
    cudaGetSymbolAddress((void**)&wvh, g_wvh);
    cudaGetSymbolAddress((void**)&woh, g_woh);

    // 1) converts (natural layouts; no transposes)
    k_conv<<<1024, 256>>>((const float4*)x,  (uint4*)xh,  NTOK * DIM / 8);
    k_conv<<<1024, 256>>>((const float4*)wq, (uint4*)wqh, DIM * DIM / 8);
    k_conv<<<1024, 256>>>((const float4*)wk, (uint4*)wkh, DIM * KVD / 8);
    k_conv<<<1024, 256>>>((const float4*)wv, (uint4*)wvh, DIM * KVD / 8);
    k_conv<<<1024, 256>>>((const float4*)wo, (uint4*)woh, DIM * DIM / 8);

    // 2) fused QKV projection (rope fused for Q/K)
    k_qkv<<<dim3(NTOT / 128, NTOK / 128), 256, SMEM_PJ>>>(fc, fs);

    // 3) fused attention
    k_flash<<<dim3(SEQ / 128, BATCH * NH), 256, SMEM_FL>>>();

    // 4) output projection -> fp32 d_out
    k_projo<<<dim3(DIM / 128, DIM / 128), 256, SMEM_PJ>>>(out);
}